// round 11
// baseline (speedup 1.0000x reference)
#include <cuda_runtime.h>
#include <cstdint>

// Round 10: extend R7's contiguity win one doubling: 4 consecutive float4s
// per thread per stream (64B/thread, 2KB/warp-step contiguous), grid-stride
// kept for chip-wide lockstep page sharing (R9 showed private chunks regress).
// launch_bounds(256,4): 32 regs payload fits the 64-reg cap cleanly.
// Predict DRAM 83.6 -> ~85.5%, kernel 41.1 -> ~40.2, dur -> ~42.5us.

__global__ void rw_zero_kernel(float* out) {
    out[0] = 0.0f;
}

__device__ __forceinline__ float bce_w(float x, int h, int mid, float t) {
    float ax  = fabsf(x);
    float e   = __expf(-ax);
    float sp  = __logf(1.0f + e);             // log1p(exp(-|x|)), e in (0,1]
    float bce = fmaxf(x, 0.0f) - x * t + sp;
    return (h >= mid) ? (bce + bce) : bce;    // weight 2 or 1
}

__global__ __launch_bounds__(256, 4)
void rw_loss_kernel(const float4* __restrict__ x4,
                    const int4*  __restrict__ h4,
                    const int*   __restrict__ target_p,
                    const int*   __restrict__ H_p,
                    float*       __restrict__ out,
                    int nvec16, float inv_n) {
    const float t   = (float)(*target_p);
    const int   mid = (*H_p) >> 1;

    const int stride = gridDim.x * blockDim.x;
    float acc = 0.0f;

    // Each j handles 16 elements: 4 consecutive float4/int4 per stream
    // (64B contiguous per thread). 8 independent LDG.128 batched up front.
    for (int j = blockIdx.x * blockDim.x + threadIdx.x; j < nvec16; j += stride) {
        const int base = 4 * j;
        float4 a0 = __ldcs(&x4[base]);
        float4 a1 = __ldcs(&x4[base + 1]);
        float4 a2 = __ldcs(&x4[base + 2]);
        float4 a3 = __ldcs(&x4[base + 3]);
        int4   b0 = __ldcs(&h4[base]);
        int4   b1 = __ldcs(&h4[base + 1]);
        int4   b2 = __ldcs(&h4[base + 2]);
        int4   b3 = __ldcs(&h4[base + 3]);

        acc += bce_w(a0.x, b0.x, mid, t);
        acc += bce_w(a0.y, b0.y, mid, t);
        acc += bce_w(a0.z, b0.z, mid, t);
        acc += bce_w(a0.w, b0.w, mid, t);
        acc += bce_w(a1.x, b1.x, mid, t);
        acc += bce_w(a1.y, b1.y, mid, t);
        acc += bce_w(a1.z, b1.z, mid, t);
        acc += bce_w(a1.w, b1.w, mid, t);
        acc += bce_w(a2.x, b2.x, mid, t);
        acc += bce_w(a2.y, b2.y, mid, t);
        acc += bce_w(a2.z, b2.z, mid, t);
        acc += bce_w(a2.w, b2.w, mid, t);
        acc += bce_w(a3.x, b3.x, mid, t);
        acc += bce_w(a3.y, b3.y, mid, t);
        acc += bce_w(a3.z, b3.z, mid, t);
        acc += bce_w(a3.w, b3.w, mid, t);
    }

    // warp reduction
    #pragma unroll
    for (int off = 16; off > 0; off >>= 1)
        acc += __shfl_xor_sync(0xFFFFFFFF, acc, off);

    __shared__ float warp_sums[8];
    const int lane = threadIdx.x & 31;
    const int wid  = threadIdx.x >> 5;
    if (lane == 0) warp_sums[wid] = acc;
    __syncthreads();

    if (wid == 0) {
        float v = (lane < 8) ? warp_sums[lane] : 0.0f;
        #pragma unroll
        for (int off = 4; off > 0; off >>= 1)
            v += __shfl_xor_sync(0xFFFFFFFF, v, off);
        if (lane == 0)
            atomicAdd(out, v * inv_n);
    }
}

extern "C" void kernel_launch(void* const* d_in, const int* in_sizes, int n_in,
                              void* d_out, int out_size) {
    const float* x      = (const float*)d_in[0];   // logits, N fp32
    const int*   target = (const int*)d_in[1];     // scalar int
    const int*   hidx   = (const int*)d_in[2];     // height_indices, N int32
    const int*   Hp     = (const int*)d_in[3];     // scalar int
    float* out = (float*)d_out;

    const int n = in_sizes[0];
    const int nvec16 = n / 16;   // N divisible by 16
    const float inv_n = 1.0f / (float)n;

    rw_zero_kernel<<<1, 1>>>(out);

    const int threads = 256;
    const int blocks  = 592;  // 148 SMs * 4
    rw_loss_kernel<<<blocks, threads>>>(
        (const float4*)x, (const int4*)hidx, target, Hp, out, nvec16, inv_n);
}

// round 12
// speedup vs baseline: 1.0559x; 1.0559x over previous
#include <cuda_runtime.h>
#include <cstdint>

// Round 11: R7's optimal layout (32B/thread/stream, 1KB/warp-step, grid-stride,
// 48 warps/SM) with Blackwell 256-bit loads (ld.global.cs.v8) — same bytes,
// half the LSU issues and L1tex wavefront queue entries.
// Predict DRAM 83.6 -> ~85%, kernel 41.1 -> ~40.3, dur -> ~43.0us.

__global__ void rw_zero_kernel(float* out) {
    out[0] = 0.0f;
}

__device__ __forceinline__ void ldg256_f32_cs(const float4* p, float4& lo, float4& hi) {
    asm volatile("ld.global.cs.v8.f32 {%0,%1,%2,%3,%4,%5,%6,%7}, [%8];"
                 : "=f"(lo.x), "=f"(lo.y), "=f"(lo.z), "=f"(lo.w),
                   "=f"(hi.x), "=f"(hi.y), "=f"(hi.z), "=f"(hi.w)
                 : "l"(p));
}

__device__ __forceinline__ void ldg256_b32_cs(const int4* p, int4& lo, int4& hi) {
    asm volatile("ld.global.cs.v8.b32 {%0,%1,%2,%3,%4,%5,%6,%7}, [%8];"
                 : "=r"(lo.x), "=r"(lo.y), "=r"(lo.z), "=r"(lo.w),
                   "=r"(hi.x), "=r"(hi.y), "=r"(hi.z), "=r"(hi.w)
                 : "l"(p));
}

__device__ __forceinline__ float bce_w(float x, int h, int mid, float t) {
    float ax  = fabsf(x);
    float e   = __expf(-ax);
    float sp  = __logf(1.0f + e);             // log1p(exp(-|x|)), e in (0,1]
    float bce = fmaxf(x, 0.0f) - x * t + sp;
    return (h >= mid) ? (bce + bce) : bce;    // weight 2 or 1
}

__global__ __launch_bounds__(256, 6)
void rw_loss_kernel(const float4* __restrict__ x4,
                    const int4*  __restrict__ h4,
                    const int*   __restrict__ target_p,
                    const int*   __restrict__ H_p,
                    float*       __restrict__ out,
                    int nvec8, float inv_n) {
    const float t   = (float)(*target_p);
    const int   mid = (*H_p) >> 1;

    const int stride = gridDim.x * blockDim.x;
    float acc = 0.0f;

    // Each j handles 8 elements: one 32B (256-bit) load per stream.
    for (int j = blockIdx.x * blockDim.x + threadIdx.x; j < nvec8; j += stride) {
        const int base = 2 * j;
        float4 a0, a1;
        int4   b0, b1;
        ldg256_f32_cs(&x4[base], a0, a1);
        ldg256_b32_cs(&h4[base], b0, b1);

        acc += bce_w(a0.x, b0.x, mid, t);
        acc += bce_w(a0.y, b0.y, mid, t);
        acc += bce_w(a0.z, b0.z, mid, t);
        acc += bce_w(a0.w, b0.w, mid, t);
        acc += bce_w(a1.x, b1.x, mid, t);
        acc += bce_w(a1.y, b1.y, mid, t);
        acc += bce_w(a1.z, b1.z, mid, t);
        acc += bce_w(a1.w, b1.w, mid, t);
    }

    // warp reduction
    #pragma unroll
    for (int off = 16; off > 0; off >>= 1)
        acc += __shfl_xor_sync(0xFFFFFFFF, acc, off);

    __shared__ float warp_sums[8];
    const int lane = threadIdx.x & 31;
    const int wid  = threadIdx.x >> 5;
    if (lane == 0) warp_sums[wid] = acc;
    __syncthreads();

    if (wid == 0) {
        float v = (lane < 8) ? warp_sums[lane] : 0.0f;
        #pragma unroll
        for (int off = 4; off > 0; off >>= 1)
            v += __shfl_xor_sync(0xFFFFFFFF, v, off);
        if (lane == 0)
            atomicAdd(out, v * inv_n);
    }
}

extern "C" void kernel_launch(void* const* d_in, const int* in_sizes, int n_in,
                              void* d_out, int out_size) {
    const float* x      = (const float*)d_in[0];   // logits, N fp32
    const int*   target = (const int*)d_in[1];     // scalar int
    const int*   hidx   = (const int*)d_in[2];     // height_indices, N int32
    const int*   Hp     = (const int*)d_in[3];     // scalar int
    float* out = (float*)d_out;

    const int n = in_sizes[0];
    const int nvec8 = n / 8;   // N divisible by 8
    const float inv_n = 1.0f / (float)n;

    rw_zero_kernel<<<1, 1>>>(out);

    const int threads = 256;
    const int blocks  = 888;  // 148 SMs * 6
    rw_loss_kernel<<<blocks, threads>>>(
        (const float4*)x, (const int4*)hidx, target, Hp, out, nvec8, inv_n);
}